// round 9
// baseline (speedup 1.0000x reference)
// O3onO2 tensor product — fused fp32 kernel, f32x2-packed FMAs, TILE_M=32,
// 2 CTAs/SM. v9: z column stride 36 floats; each warp owns 4 consecutive
// rows -> ONE LDS.128 broadcast per (k,zc) (halves GEMM z crossbar traffic).
#include <cuda_runtime.h>
#include <cstdint>

#define NROWS    65536
#define TILE_M   32
#define NTHREADS 256
#define W_STRIDE 66
#define Z_STRIDE 36                         // floats per z column (16B aligned)
#define W_OFF    0
#define Z_OFF    4224                       // 64*66 floats for W
#define SMEM_FLOATS (Z_OFF + 64 * 7 * Z_STRIDE)   // 4224 + 16128 = 20352
#define SMEM_BYTES  (SMEM_FLOATS * 4)             // 81408 B -> 2 CTAs/SM

__device__ __forceinline__ constexpr int blk_off(int l) {
    return l == 0 ? 0 : (l == 1 ? 64 : (l == 2 ? 256 : 576));
}

__device__ __forceinline__ unsigned long long dup2(float a) {
    unsigned long long r;
    asm("mov.b64 %0, {%1, %1};" : "=l"(r) : "f"(a));
    return r;
}
__device__ __forceinline__ void fma2(unsigned long long& d,
                                     unsigned long long a,
                                     unsigned long long b) {
    asm("fma.rn.f32x2 %0, %1, %2, %0;" : "+l"(d) : "l"(a), "l"(b));
}

// ---- phase 1 of each li: stage W (transposed, L2-hot) + combine z from global
template <int LO, int LI>
__device__ __forceinline__ void stage_combine(
    float* __restrict__ sm, const float* __restrict__ gx,
    const float* __restrict__ wts, const float* __restrict__ hz,
    const float* __restrict__ hpg, const float* __restrict__ hng)
{
    constexpr int W21 = 2 * LI + 1;
    constexpr int MM  = LO < LI ? LO : LI;
    constexpr int NZ  = 2 * MM + 1;
    constexpr int P   = LO * 4 + LI;
    const int tid = threadIdx.x;

    // stage W transposed: ws[i*66 + o] = W[o][i]
    const float* gw = wts + P * 4096;
#pragma unroll
    for (int s = 0; s < 16; s++) {
        const int idx = tid + s * NTHREADS;
        const int o = idx >> 6, i = idx & 63;
        sm[W_OFF + i * W_STRIDE + o] = __ldg(gw + idx);
    }

    // combine: z[(k*NZ+zc)*36 + r] = h-combo of x[r, k*(2LI+1) + LI +- m]
    const float h0 = __ldg(hz + P);
    float hp[MM ? MM : 1], hn[MM ? MM : 1];
#pragma unroll
    for (int m = 0; m < MM; m++) {
        hp[m] = __ldg(hpg + P * 3 + m);
        hn[m] = __ldg(hng + P * 3 + m);
    }
    float* zs = sm + Z_OFF;
#pragma unroll
    for (int s = 0; s < (64 * TILE_M) / NTHREADS; s++) {
        const int it = tid + s * NTHREADS;
        const int k = it & 63;
        const int r = it >> 6;
        const float* xb = gx + (size_t)r * 1024 + k * W21 + LI;
        float* zcol = zs + (k * NZ) * Z_STRIDE + r;
        zcol[0] = h0 * __ldg(xb);
#pragma unroll
        for (int m = 1; m <= MM; m++) {
            const float xp = __ldg(xb + m);
            const float xn = __ldg(xb - m);
            zcol[(2 * m - 1) * Z_STRIDE] = hp[m - 1] * xp + hn[m - 1] * xn;
            zcol[(2 * m) * Z_STRIDE]     = hp[m - 1] * xn - hn[m - 1] * xp;
        }
    }
}

// ---- phase 2: register GEMM. warp rg owns rows 4rg..4rg+3 (one LDS.128
// broadcast per (k,zc)); lane og owns out channels og*2, og*2+1.
template <int LO, int LI>
__device__ __forceinline__ void gemm(
    const float* __restrict__ sm,
    unsigned long long (&acc)[2][2][2 * LO + 1], int rg, int og)
{
    constexpr int MM = LO < LI ? LO : LI;
    constexpr int NZ = 2 * MM + 1;
    const ulonglong2* zb =
        reinterpret_cast<const ulonglong2*>(sm + Z_OFF);  // 16B units
    const float* wsl = sm + W_OFF + og * 2;
#pragma unroll 4
    for (int k = 0; k < 64; k++) {
        const float2 wv = *reinterpret_cast<const float2*>(wsl + k * W_STRIDE);
        const unsigned long long w0 = dup2(wv.x);
        const unsigned long long w1 = dup2(wv.y);
#pragma unroll
        for (int zc = 0; zc < NZ; zc++) {
            const int c = (zc == 0) ? LO
                         : ((zc & 1) ? LO + (zc + 1) / 2 : LO - zc / 2);
            const int col = k * NZ + zc;
            const ulonglong2 z = zb[col * (Z_STRIDE / 4) + rg];  // rows 4rg..+3
            fma2(acc[0][0][c], z.x, w0);
            fma2(acc[0][1][c], z.x, w1);
            fma2(acc[1][0][c], z.y, w0);
            fma2(acc[1][1][c], z.y, w1);
        }
    }
}

template <int LO>
__device__ __forceinline__ void run(
    float* __restrict__ sm, const float* __restrict__ x,
    const float* __restrict__ wts, const float* __restrict__ hz,
    const float* __restrict__ hpg, const float* __restrict__ hng,
    float* __restrict__ out, int tile)
{
    constexpr int NC  = 2 * LO + 1;
    constexpr int SEG = 64 * NC;
    constexpr int NQ  = SEG / 4;
    const int tid = threadIdx.x;
    const int rg  = tid >> 5;
    const int og  = tid & 31;
    const float* gx = x + (size_t)tile * TILE_M * 1024;

    unsigned long long acc[2][2][NC];
#pragma unroll
    for (int a = 0; a < 2; a++)
#pragma unroll
        for (int b = 0; b < 2; b++)
#pragma unroll
            for (int c = 0; c < NC; c++) acc[a][b][c] = 0ull;

    stage_combine<LO, 0>(sm, gx + blk_off(0), wts, hz, hpg, hng);
    __syncthreads();
    gemm<LO, 0>(sm, acc, rg, og);
    __syncthreads();
    stage_combine<LO, 1>(sm, gx + blk_off(1), wts, hz, hpg, hng);
    __syncthreads();
    gemm<LO, 1>(sm, acc, rg, og);
    __syncthreads();
    stage_combine<LO, 2>(sm, gx + blk_off(2), wts, hz, hpg, hng);
    __syncthreads();
    gemm<LO, 2>(sm, acc, rg, og);
    __syncthreads();
    stage_combine<LO, 3>(sm, gx + blk_off(3), wts, hz, hpg, hng);
    __syncthreads();
    gemm<LO, 3>(sm, acc, rg, og);

    // ---- output: stage tile in smem (global layout), coalesced f4 stores ----
    __syncthreads();                      // everyone done reading z
    float* smo = sm + Z_OFF;
#pragma unroll
    for (int h = 0; h < 2; h++) {         // acc half -> row pair
        const int rbase = rg * 4 + h * 2;
#pragma unroll
        for (int oo = 0; oo < 2; oo++) {
            const int o = og * 2 + oo;
#pragma unroll
            for (int c = 0; c < NC; c++) {
                const unsigned long long v = acc[h][oo][c];
                smo[rbase * SEG + o * NC + c] =
                    __uint_as_float((unsigned)(v & 0xffffffffu));
                smo[(rbase + 1) * SEG + o * NC + c] =
                    __uint_as_float((unsigned)(v >> 32));
            }
        }
    }
    __syncthreads();
    float* go = out + (size_t)tile * TILE_M * 1024 + blk_off(LO);
#pragma unroll
    for (int rr = 0; rr < TILE_M / 8; rr++) {
        const int r = rg * (TILE_M / 8) + rr;
        for (int j = og; j < NQ; j += 32) {
            *reinterpret_cast<float4*>(go + (size_t)r * 1024 + j * 4) =
                *reinterpret_cast<const float4*>(smo + r * SEG + j * 4);
        }
    }
}

extern "C" __global__ void __launch_bounds__(NTHREADS, 2)
tp_kernel(const float* __restrict__ x, const float* __restrict__ wts,
          const float* __restrict__ hz, const float* __restrict__ hpg,
          const float* __restrict__ hng, float* __restrict__ out)
{
    extern __shared__ float sm[];
    const int tile = blockIdx.y;
    switch (blockIdx.x) {
        case 0: run<0>(sm, x, wts, hz, hpg, hng, out, tile); break;
        case 1: run<1>(sm, x, wts, hz, hpg, hng, out, tile); break;
        case 2: run<2>(sm, x, wts, hz, hpg, hng, out, tile); break;
        default: run<3>(sm, x, wts, hz, hpg, hng, out, tile); break;
    }
}

extern "C" void kernel_launch(void* const* d_in, const int* in_sizes, int n_in,
                              void* d_out, int out_size)
{
    const float* x   = (const float*)d_in[0];
    const float* wts = (const float*)d_in[1];
    const float* hz  = (const float*)d_in[2];
    const float* hpg = (const float*)d_in[3];
    const float* hng = (const float*)d_in[4];
    float* out = (float*)d_out;

    cudaFuncSetAttribute(tp_kernel, cudaFuncAttributeMaxDynamicSharedMemorySize,
                         SMEM_BYTES);
    dim3 grid(4, NROWS / TILE_M);
    tp_kernel<<<grid, NTHREADS, SMEM_BYTES>>>(x, wts, hz, hpg, hng, out);
}

// round 10
// speedup vs baseline: 1.0352x; 1.0352x over previous
// O3onO2 tensor product — fp32 SIMT, f32x2 FMAs, TILE_M=32, 2 CTAs/SM.
// v10: per-thread tile = 1 row-pair x 4 out-channels (lane = och-group 0..15,
// half-warp = row-pair) -> per (k,zc): 1 LDS.64 z + 4 FFMA2; W via one
// aligned LDS.128 per k (stride 68). Halves GEMM L1 wavefronts vs v6.
#include <cuda_runtime.h>
#include <cstdint>

#define NROWS    65536
#define TILE_M   32
#define NTHREADS 256
#define W_STRIDE 68                         // floats; multiple of 4 for LDS.128
#define Z_STRIDE 34                         // floats per z column
#define W_OFF    0
#define Z_OFF    (64 * W_STRIDE)            // 4352 floats
#define SMEM_FLOATS (Z_OFF + 64 * 7 * Z_STRIDE)   // 4352 + 15232 = 19584
#define SMEM_BYTES  (SMEM_FLOATS * 4)             // 78336 B -> 2 CTAs/SM

__device__ __forceinline__ constexpr int blk_off(int l) {
    return l == 0 ? 0 : (l == 1 ? 64 : (l == 2 ? 256 : 576));
}

__device__ __forceinline__ unsigned long long dup2(float a) {
    unsigned long long r;
    asm("mov.b64 %0, {%1, %1};" : "=l"(r) : "f"(a));
    return r;
}
__device__ __forceinline__ void fma2(unsigned long long& d,
                                     unsigned long long a,
                                     unsigned long long b) {
    asm("fma.rn.f32x2 %0, %1, %2, %0;" : "+l"(d) : "l"(a), "l"(b));
}

// ---- phase 1 of each li: stage W (transposed) + combine z from global ----
template <int LO, int LI>
__device__ __forceinline__ void stage_combine(
    float* __restrict__ sm, const float* __restrict__ gx,
    const float* __restrict__ wts, const float* __restrict__ hz,
    const float* __restrict__ hpg, const float* __restrict__ hng)
{
    constexpr int W21 = 2 * LI + 1;
    constexpr int MM  = LO < LI ? LO : LI;
    constexpr int NZ  = 2 * MM + 1;
    constexpr int P   = LO * 4 + LI;
    const int tid = threadIdx.x;

    // stage W transposed: ws[i*68 + o] = W[o][i]  (conflict-free writes)
    const float* gw = wts + P * 4096;
#pragma unroll
    for (int s = 0; s < 16; s++) {
        const int idx = tid + s * NTHREADS;
        const int o = idx >> 6, i = idx & 63;
        sm[W_OFF + i * W_STRIDE + o] = __ldg(gw + idx);
    }

    // combine: z[(k*NZ+zc)*34 + r] = h-combo of x[r, k*(2LI+1) + LI +- m]
    const float h0 = __ldg(hz + P);
    float hp[MM ? MM : 1], hn[MM ? MM : 1];
#pragma unroll
    for (int m = 0; m < MM; m++) {
        hp[m] = __ldg(hpg + P * 3 + m);
        hn[m] = __ldg(hng + P * 3 + m);
    }
    float* zs = sm + Z_OFF;
#pragma unroll
    for (int s = 0; s < (64 * TILE_M) / NTHREADS; s++) {
        const int it = tid + s * NTHREADS;
        const int k = it & 63;
        const int r = it >> 6;
        const float* xb = gx + (size_t)r * 1024 + k * W21 + LI;
        float* zcol = zs + (k * NZ) * Z_STRIDE + r;
        zcol[0] = h0 * __ldg(xb);
#pragma unroll
        for (int m = 1; m <= MM; m++) {
            const float xp = __ldg(xb + m);
            const float xn = __ldg(xb - m);
            zcol[(2 * m - 1) * Z_STRIDE] = hp[m - 1] * xp + hn[m - 1] * xn;
            zcol[(2 * m) * Z_STRIDE]     = hp[m - 1] * xn - hn[m - 1] * xp;
        }
    }
}

// ---- phase 2: register GEMM. Thread = (row-pair rp, 4 out-channels og*4..+3).
template <int LO, int LI>
__device__ __forceinline__ void gemm(
    const float* __restrict__ sm,
    unsigned long long (&acc)[4][2 * LO + 1], int rp, int og)
{
    constexpr int MM = LO < LI ? LO : LI;
    constexpr int NZ = 2 * MM + 1;
    const unsigned long long* zb =
        reinterpret_cast<const unsigned long long*>(sm + Z_OFF);
    const float* wsl = sm + W_OFF + og * 4;
#pragma unroll 4
    for (int k = 0; k < 64; k++) {
        const float4 wv = *reinterpret_cast<const float4*>(wsl + k * W_STRIDE);
        const unsigned long long w0 = dup2(wv.x);
        const unsigned long long w1 = dup2(wv.y);
        const unsigned long long w2 = dup2(wv.z);
        const unsigned long long w3 = dup2(wv.w);
#pragma unroll
        for (int zc = 0; zc < NZ; zc++) {
            const int c = (zc == 0) ? LO
                         : ((zc & 1) ? LO + (zc + 1) / 2 : LO - zc / 2);
            const unsigned long long z = zb[(k * NZ + zc) * (Z_STRIDE / 2) + rp];
            fma2(acc[0][c], z, w0);
            fma2(acc[1][c], z, w1);
            fma2(acc[2][c], z, w2);
            fma2(acc[3][c], z, w3);
        }
    }
}

template <int LO>
__device__ __forceinline__ void run(
    float* __restrict__ sm, const float* __restrict__ x,
    const float* __restrict__ wts, const float* __restrict__ hz,
    const float* __restrict__ hpg, const float* __restrict__ hng,
    float* __restrict__ out, int tile)
{
    constexpr int NC  = 2 * LO + 1;
    constexpr int SEG = 64 * NC;
    constexpr int NQ  = SEG / 4;
    const int tid = threadIdx.x;
    const int rg  = tid >> 5;               // warp id
    const int lid = tid & 31;
    const int og  = lid & 15;               // 4-channel group
    const int rp  = rg * 2 + (lid >> 4);    // row-pair index 0..15
    const float* gx = x + (size_t)tile * TILE_M * 1024;

    unsigned long long acc[4][NC];
#pragma unroll
    for (int a = 0; a < 4; a++)
#pragma unroll
        for (int c = 0; c < NC; c++) acc[a][c] = 0ull;

    stage_combine<LO, 0>(sm, gx + blk_off(0), wts, hz, hpg, hng);
    __syncthreads();
    gemm<LO, 0>(sm, acc, rp, og);
    __syncthreads();
    stage_combine<LO, 1>(sm, gx + blk_off(1), wts, hz, hpg, hng);
    __syncthreads();
    gemm<LO, 1>(sm, acc, rp, og);
    __syncthreads();
    stage_combine<LO, 2>(sm, gx + blk_off(2), wts, hz, hpg, hng);
    __syncthreads();
    gemm<LO, 2>(sm, acc, rp, og);
    __syncthreads();
    stage_combine<LO, 3>(sm, gx + blk_off(3), wts, hz, hpg, hng);
    __syncthreads();
    gemm<LO, 3>(sm, acc, rp, og);

    // ---- output: stage tile in smem (global layout), coalesced f4 stores ----
    __syncthreads();                      // everyone done reading z
    float* smo = sm + Z_OFF;
    const int r0 = rp * 2;                // first of the thread's two rows
#pragma unroll
    for (int oo = 0; oo < 4; oo++) {
        const int o = og * 4 + oo;
#pragma unroll
        for (int c = 0; c < NC; c++) {
            const unsigned long long v = acc[oo][c];
            smo[r0 * SEG + o * NC + c] =
                __uint_as_float((unsigned)(v & 0xffffffffu));
            smo[(r0 + 1) * SEG + o * NC + c] =
                __uint_as_float((unsigned)(v >> 32));
        }
    }
    __syncthreads();
    float* go = out + (size_t)tile * TILE_M * 1024 + blk_off(LO);
#pragma unroll
    for (int rr = 0; rr < TILE_M / 8; rr++) {
        const int r = rg * (TILE_M / 8) + rr;
        for (int j = lid; j < NQ; j += 32) {
            *reinterpret_cast<float4*>(go + (size_t)r * 1024 + j * 4) =
                *reinterpret_cast<const float4*>(smo + r * SEG + j * 4);
        }
    }
}

extern "C" __global__ void __launch_bounds__(NTHREADS, 2)
tp_kernel(const float* __restrict__ x, const float* __restrict__ wts,
          const float* __restrict__ hz, const float* __restrict__ hpg,
          const float* __restrict__ hng, float* __restrict__ out)
{
    extern __shared__ float sm[];
    const int tile = blockIdx.y;
    switch (blockIdx.x) {
        case 0: run<0>(sm, x, wts, hz, hpg, hng, out, tile); break;
        case 1: run<1>(sm, x, wts, hz, hpg, hng, out, tile); break;
        case 2: run<2>(sm, x, wts, hz, hpg, hng, out, tile); break;
        default: run<3>(sm, x, wts, hz, hpg, hng, out, tile); break;
    }
}

extern "C" void kernel_launch(void* const* d_in, const int* in_sizes, int n_in,
                              void* d_out, int out_size)
{
    const float* x   = (const float*)d_in[0];
    const float* wts = (const float*)d_in[1];
    const float* hz  = (const float*)d_in[2];
    const float* hpg = (const float*)d_in[3];
    const float* hng = (const float*)d_in[4];
    float* out = (float*)d_out;

    cudaFuncSetAttribute(tp_kernel, cudaFuncAttributeMaxDynamicSharedMemorySize,
                         SMEM_BYTES);
    dim3 grid(4, NROWS / TILE_M);
    tp_kernel<<<grid, NTHREADS, SMEM_BYTES>>>(x, wts, hz, hpg, hng, out);
}